// round 14
// baseline (speedup 1.0000x reference)
#include <cuda_runtime.h>
#include <cstdint>

// DiverseSiblingsSearch on GB300 — cp.async (LDGSTS) 6-stage smem pipeline:
// bytes-in-flight decoupled from register pressure. Single DRAM pass.
// lprobs: (128, 5, 50257) f32, scores: (128, 5, 10) f32, step: int scalar (=10).
// Output (f32): final_scores (128,10) | final_indices (128,10) | final_beams (128,10).

#define BSZ     128
#define BEAM    5
#define VOCAB   50257
#define KSEL    10
#define ROWS    (BSZ * BEAM)
#define T       256
#define NWARP   (T / 32)
#define NSTAGE  6
#define CHUNKV  512                    // float4 per chunk (8 KB)
#define CAP     512
#define DIV_RATE 0.5f
#define NEG_INF __int_as_float(0xff800000u)
#define IDX_INF 0x7fffffff

// Dynamic smem layout (bytes): sbuf 6*512*16 = 49152 | cval 2048 | cidx 2048 | swtop 64 | thr/count
#define OFF_CVAL  49152
#define OFF_CIDX  51200
#define OFF_SWTOP 53248
#define OFF_STHR  53312
#define OFF_SCNT  53316
#define DSM_BYTES 53440

// Inter-block scratch (no allocations allowed).
__device__ float g_cand_val[ROWS * KSEL];
__device__ int   g_cand_idx[ROWS * KSEL];
__device__ int   g_batch_done[BSZ];            // zero-init; reset by finisher each replay

__device__ __forceinline__ bool better(float v1, int i1, float v2, int i2) {
    // JAX top_k stability: larger value wins; ties -> smaller index wins.
    return (v1 > v2) || (v1 == v2 && i1 < i2);
}

__device__ __forceinline__ float4 max4(float4 a, float4 b) {
    return make_float4(fmaxf(a.x, b.x), fmaxf(a.y, b.y), fmaxf(a.z, b.z), fmaxf(a.w, b.w));
}

__device__ __forceinline__ void cp_async16(uint32_t saddr, const float4* g) {
    asm volatile("cp.async.cg.shared.global [%0], [%1], 16;" :: "r"(saddr), "l"(g));
}

__global__ __launch_bounds__(T, 4)
void dss_kernel(const float* __restrict__ lprobs,
                const float* __restrict__ scores,
                const int* __restrict__ step_ptr,
                int score_last_dim,
                float* __restrict__ out) {
    extern __shared__ char dsm[];
    float4*   sbuf   = reinterpret_cast<float4*>(dsm);
    float*    cval   = reinterpret_cast<float*>(dsm + OFF_CVAL);
    int*      cidx   = reinterpret_cast<int*>(dsm + OFF_CIDX);
    float*    swtop  = reinterpret_cast<float*>(dsm + OFF_SWTOP);
    float*    sthr   = reinterpret_cast<float*>(dsm + OFF_STHR);
    unsigned* scount = reinterpret_cast<unsigned*>(dsm + OFF_SCNT);

    const int row   = blockIdx.x;               // row = batch * BEAM + beam
    const int batch = row / BEAM;
    const int tid   = threadIdx.x;
    const int lane  = tid & 31;
    const int wid   = tid >> 5;
    const float* __restrict__ rp = lprobs + (size_t)row * VOCAB;

    if (tid == 0) *scount = 0u;

    // Alignment peel: row*VOCAB mod 4 == row mod 4.
    const int P     = (4 - (row & 3)) & 3;      // head elements (scalar)
    const int nv    = (VOCAB - P) >> 2;         // aligned float4 count (>= 12563)
    const int tailn = (VOCAB - P) & 3;          // tail elements (scalar)
    const float4* __restrict__ rp4 = reinterpret_cast<const float4*>(rp + P);
    const int nchunk = (nv + CHUNKV - 1) / CHUNKV;   // ~25

    const uint32_t sb = (uint32_t)__cvta_generic_to_shared(sbuf);

    // Stage chunk c into stage c%NSTAGE; each thread copies ONLY its 2 slots.
    auto stage = [&](int c) {
        int st   = c % NSTAGE;
        int base = c * CHUNKV;
        int i0 = base + tid, i1 = base + T + tid;
        uint32_t d0 = sb + (uint32_t)(st * CHUNKV + tid) * 16u;
        if (i0 < nv) cp_async16(d0, rp4 + i0);
        if (i1 < nv) cp_async16(d0 + T * 16u, rp4 + i1);
        asm volatile("cp.async.commit_group;");
    };

    // ---- Phase A: stage seg1 = chunks 0..5 (12288 elements), all in flight ----
#pragma unroll
    for (int c = 0; c < NSTAGE; ++c) stage(c);
    asm volatile("cp.async.wait_group 0;");     // own copies all landed

    // Per-thread max over its OWN 12 staged slots (no cross-thread reads -> no sync).
    float4 Mx = make_float4(NEG_INF, NEG_INF, NEG_INF, NEG_INF);
    float4 My = Mx;
#pragma unroll
    for (int c = 0; c < NSTAGE; ++c) {
        Mx = max4(Mx, sbuf[c * CHUNKV + tid]);
        My = max4(My, sbuf[c * CHUNKV + T + tid]);
    }
    Mx = max4(Mx, My);
    float m = fmaxf(fmaxf(Mx.x, Mx.y), fmaxf(Mx.z, Mx.w));

    // ---- Per-warp top-2 of per-thread seg1 maxima (2 distinct elements/warp) ----
    {
        float w1 = m;
        for (int off = 16; off; off >>= 1) w1 = fmaxf(w1, __shfl_xor_sync(0xffffffffu, w1, off));
        unsigned holders = __ballot_sync(0xffffffffu, m == w1);
        int first = __ffs(holders) - 1;
        float m2 = (lane == first) ? NEG_INF : m;
        float w2 = m2;
        for (int off = 16; off; off >>= 1) w2 = fmaxf(w2, __shfl_xor_sync(0xffffffffu, w2, off));
        if (lane == 0) { swtop[wid] = w1; swtop[NWARP + wid] = w2; }
    }
    __syncthreads();

    // ---- thr = 10th largest of 16 distinct seg1 elements (subset of row =>
    // 10th(sample) <= 10th(row): conservative row-wide). ----
    if (tid < 32) {
        float x = (lane < 2 * NWARP) ? swtop[lane] : NEG_INF;
        float t = NEG_INF;
        for (int r = 0; r < KSEL; ++r) {
            float bv = x;
            for (int off = 16; off; off >>= 1) bv = fmaxf(bv, __shfl_xor_sync(0xffffffffu, bv, off));
            unsigned holders = __ballot_sync(0xffffffffu, x == bv);
            int first = __ffs(holders) - 1;
            if (lane == first) x = NEG_INF;     // retire one instance
            t = bv;
        }
        if (lane == 0) *sthr = t;
    }
    __syncthreads();
    const float thr = *sthr;

    // Quad filter: prefilter on quad max, push survivors (exact value+index).
    auto filter_quad = [&](float4 a, int i0) {
        float qm = fmaxf(fmaxf(a.x, a.y), fmaxf(a.z, a.w));
        if (qm >= thr) {                        // rare (~0.5% of quads)
            if (a.x >= thr) { unsigned p = atomicAdd(scount, 1u); if (p < CAP) { cval[p] = a.x; cidx[p] = i0; } }
            if (a.y >= thr) { unsigned p = atomicAdd(scount, 1u); if (p < CAP) { cval[p] = a.y; cidx[p] = i0 + 1; } }
            if (a.z >= thr) { unsigned p = atomicAdd(scount, 1u); if (p < CAP) { cval[p] = a.z; cidx[p] = i0 + 2; } }
            if (a.w >= thr) { unsigned p = atomicAdd(scount, 1u); if (p < CAP) { cval[p] = a.w; cidx[p] = i0 + 3; } }
        }
    };
    // Consume chunk c: each thread filters ONLY its own 2 staged slots.
    auto consume = [&](int c) {
        int st   = c % NSTAGE;
        int base = c * CHUNKV;
        int i0 = base + tid, i1 = base + T + tid;
        if (i0 < nv) filter_quad(sbuf[st * CHUNKV + tid],     P + 4 * i0);
        if (i1 < nv) filter_quad(sbuf[st * CHUNKV + T + tid], P + 4 * i1);
    };

    // ---- Phase B: filter staged seg1 chunks, refilling the ring behind them ----
#pragma unroll
    for (int c = 0; c < NSTAGE; ++c) { consume(c); stage(c + NSTAGE); }

    // ---- Main pipeline: chunks NSTAGE..nchunk-1, ring depth NSTAGE ----
    for (int c = NSTAGE; c < nchunk; ++c) {
        asm volatile("cp.async.wait_group %0;" :: "n"(NSTAGE - 1));  // chunk c landed
        consume(c);
        if (c + NSTAGE < nchunk) stage(c + NSTAGE);
        else asm volatile("cp.async.commit_group;");   // empty group: uniform accounting
    }

    if (tid == 0) {          // head elements, exact test
        for (int i = 0; i < P; ++i) {
            float x = rp[i];
            if (x >= thr) { unsigned p = atomicAdd(scount, 1u); if (p < CAP) { cval[p] = x; cidx[p] = i; } }
        }
    }
    if (tid == 1) {          // tail elements, exact test
        for (int q = 0; q < tailn; ++q) {
            int i = P + 4 * nv + q;
            float x = rp[i];
            if (x >= thr) { unsigned p = atomicAdd(scount, 1u); if (p < CAP) { cval[p] = x; cidx[p] = i; } }
        }
    }
    __syncthreads();

    const unsigned cnt   = *scount;
    const int      stepv = step_ptr ? *step_ptr : KSEL;
    const float    base  = scores[row * score_last_dim + (stepv - 1)];

    if (cnt > CAP) {
        // Pathological mass-tie fallback: exact serial top-10.
        if (tid == 0) {
            float val[KSEL]; int idq[KSEL];
#pragma unroll
            for (int q = 0; q < KSEL; ++q) { val[q] = NEG_INF; idq[q] = IDX_INF; }
            for (int i = 0; i < VOCAB; ++i) {
                float x = rp[i];
                if (better(x, i, val[KSEL - 1], idq[KSEL - 1])) {
                    val[KSEL - 1] = x; idq[KSEL - 1] = i;
#pragma unroll
                    for (int q = KSEL - 1; q > 0; --q) {
                        if (better(val[q], idq[q], val[q - 1], idq[q - 1])) {
                            float tv = val[q]; val[q] = val[q - 1]; val[q - 1] = tv;
                            int   ti = idq[q]; idq[q] = idq[q - 1]; idq[q - 1] = ti;
                        }
                    }
                }
            }
#pragma unroll
            for (int r = 0; r < KSEL; ++r) {
                g_cand_val[row * KSEL + r] = (val[r] + base) - (float)(r + 1) * DIV_RATE;
                g_cand_idx[row * KSEL + r] = idq[r];
            }
        }
    } else {
        // Warp-parallel stable top-10 over ~50 exact candidates.
        if (tid < 32) {
            for (int r = 0; r < KSEL; ++r) {
                float bv = NEG_INF; int bi = IDX_INF; int bp = -1;
                for (unsigned c = lane; c < cnt; c += 32) {
                    float x = cval[c]; int ix = cidx[c];
                    if (better(x, ix, bv, bi)) { bv = x; bi = ix; bp = (int)c; }
                }
                for (int off = 16; off; off >>= 1) {
                    float ov = __shfl_down_sync(0xffffffffu, bv, off);
                    int   oi = __shfl_down_sync(0xffffffffu, bi, off);
                    int   op = __shfl_down_sync(0xffffffffu, bp, off);
                    if (better(ov, oi, bv, bi)) { bv = ov; bi = oi; bp = op; }
                }
                if (lane == 0) {
                    // ((lprob + base) - penalty): reference op order -> bit-exact.
                    g_cand_val[row * KSEL + r] = (bv + base) - (float)(r + 1) * DIV_RATE;
                    g_cand_idx[row * KSEL + r] = bi;
                    cval[bp] = NEG_INF; cidx[bp] = IDX_INF;
                }
                __syncwarp();
            }
        }
    }

    // ---- Fused finisher: last beam-block of the batch does the 50->10 select ----
    int done = 0;
    if (tid == 0) {
        __threadfence();                              // release g_cand writes
        done = atomicAdd(&g_batch_done[batch], 1);
    }
    if (tid < 32) {
        done = __shfl_sync(0xffffffffu, done, 0);
        if (done == BEAM - 1) {
            __threadfence();                          // acquire peers' g_cand
            const int b50 = batch * BEAM * KSEL;
            float v0 = NEG_INF, v1 = NEG_INF;
            int   p0 = IDX_INF, p1 = IDX_INF;
            if (lane < BEAM * KSEL)      { v0 = __ldcg(&g_cand_val[b50 + lane]);      p0 = lane; }
            if (lane + 32 < BEAM * KSEL) { v1 = __ldcg(&g_cand_val[b50 + lane + 32]); p1 = lane + 32; }
            for (int r = 0; r < KSEL; ++r) {
                float bv; int bp;
                if (better(v0, p0, v1, p1)) { bv = v0; bp = p0; } else { bv = v1; bp = p1; }
                for (int off = 16; off; off >>= 1) {
                    float ov = __shfl_down_sync(0xffffffffu, bv, off);
                    int   op = __shfl_down_sync(0xffffffffu, bp, off);
                    if (better(ov, op, bv, bp)) { bv = ov; bp = op; }
                }
                bv = __shfl_sync(0xffffffffu, bv, 0);
                bp = __shfl_sync(0xffffffffu, bp, 0);
                if (lane == 0) {
                    out[batch * KSEL + r]                  = bv;                                   // scores
                    out[BSZ * KSEL + batch * KSEL + r]     = (float)__ldcg(&g_cand_idx[b50 + bp]); // indices
                    out[2 * BSZ * KSEL + batch * KSEL + r] = (float)(bp / KSEL);                   // beams
                }
                if (p0 == bp) { v0 = NEG_INF; p0 = IDX_INF; }
                if (p1 == bp) { v1 = NEG_INF; p1 = IDX_INF; }
            }
            if (lane == 0) atomicExch(&g_batch_done[batch], 0);   // reset for next replay
        }
    }
}

extern "C" void kernel_launch(void* const* d_in, const int* in_sizes, int n_in,
                              void* d_out, int out_size) {
    const float* lprobs = (const float*)d_in[0];
    const float* scores = (const float*)d_in[1];
    const int*   step   = (n_in >= 3) ? (const int*)d_in[2] : nullptr;
    const int score_last_dim = in_sizes[1] / ROWS;   // = 10

    cudaFuncSetAttribute(dss_kernel, cudaFuncAttributeMaxDynamicSharedMemorySize, DSM_BYTES);
    dss_kernel<<<ROWS, T, DSM_BYTES>>>(lprobs, scores, step, score_last_dim, (float*)d_out);
}

// round 15
// speedup vs baseline: 1.4244x; 1.4244x over previous
#include <cuda_runtime.h>
#include <cstdint>

// DiverseSiblingsSearch on GB300 — single pass, seg1-sampled threshold (R12
// structure), reshaped to T=128 x 10 blocks/SM for a guaranteed single wave.
// lprobs: (128, 5, 50257) f32, scores: (128, 5, 10) f32, step: int scalar (=10).
// Output (f32): final_scores (128,10) | final_indices (128,10) | final_beams (128,10).

#define BSZ     128
#define BEAM    5
#define VOCAB   50257
#define KSEL    10
#define ROWS    (BSZ * BEAM)
#define T       128
#define NWARP   (T / 32)               // 4
#define NQ1     24                     // seg1 = first NQ1 strided quads/thread = 12288 elems
#define CAP     512
#define DIV_RATE 0.5f
#define NEG_INF __int_as_float(0xff800000u)
#define IDX_INF 0x7fffffff

// Inter-block scratch (no allocations allowed).
__device__ float g_cand_val[ROWS * KSEL];
__device__ int   g_cand_idx[ROWS * KSEL];
__device__ int   g_batch_done[BSZ];            // zero-init; reset by finisher each replay

__device__ __forceinline__ bool better(float v1, int i1, float v2, int i2) {
    // JAX top_k stability: larger value wins; ties -> smaller index wins.
    return (v1 > v2) || (v1 == v2 && i1 < i2);
}

__device__ __forceinline__ float4 max4(float4 a, float4 b) {
    return make_float4(fmaxf(a.x, b.x), fmaxf(a.y, b.y), fmaxf(a.z, b.z), fmaxf(a.w, b.w));
}

__global__ __launch_bounds__(T, 10)
void dss_kernel(const float* __restrict__ lprobs,
                const float* __restrict__ scores,
                const int* __restrict__ step_ptr,
                int score_last_dim,
                float* __restrict__ out) {
    __shared__ float    swtop[3 * NWARP];       // per-warp top-3 of seg1 per-thread maxima
    __shared__ float    sthr;
    __shared__ unsigned scount;
    __shared__ float    cval[CAP];
    __shared__ int      cidx[CAP];

    const int row   = blockIdx.x;               // row = batch * BEAM + beam
    const int batch = row / BEAM;
    const int tid   = threadIdx.x;
    const int lane  = tid & 31;
    const int wid   = tid >> 5;
    const float* __restrict__ rp = lprobs + (size_t)row * VOCAB;

    if (tid == 0) scount = 0u;

    // Alignment peel: row*VOCAB mod 4 == row mod 4.
    const int P     = (4 - (row & 3)) & 3;      // head elements (scalar)
    const int nv    = (VOCAB - P) >> 2;         // aligned float4 count
    const int tailn = (VOCAB - P) & 3;          // tail elements (scalar)
    const float4* __restrict__ rp4 = reinterpret_cast<const float4*>(rp + P);

    // ---- Phase 1a: branchless max over seg1 (first NQ1 quads/thread) ----
    float4 M0 = make_float4(NEG_INF, NEG_INF, NEG_INF, NEG_INF);
    float4 M1 = M0, M2 = M0, M3 = M0;
#pragma unroll
    for (int j = 0; j < NQ1; j += 4) {
        float4 a = rp4[tid + j * T];
        float4 b = rp4[tid + (j + 1) * T];
        float4 c = rp4[tid + (j + 2) * T];
        float4 d = rp4[tid + (j + 3) * T];
        M0 = max4(M0, a); M1 = max4(M1, b); M2 = max4(M2, c); M3 = max4(M3, d);
    }
    M0 = max4(max4(M0, M1), max4(M2, M3));
    float m = fmaxf(fmaxf(M0.x, M0.y), fmaxf(M0.z, M0.w));

    // ---- Per-warp top-3 of per-thread seg1 maxima (3 distinct elements/warp) ----
    {
        float x = m;
        float w1 = x;
        for (int off = 16; off; off >>= 1) w1 = fmaxf(w1, __shfl_xor_sync(0xffffffffu, w1, off));
        unsigned h1 = __ballot_sync(0xffffffffu, x == w1);
        if (lane == __ffs(h1) - 1) x = NEG_INF;
        float w2 = x;
        for (int off = 16; off; off >>= 1) w2 = fmaxf(w2, __shfl_xor_sync(0xffffffffu, w2, off));
        unsigned h2 = __ballot_sync(0xffffffffu, x == w2);
        if (lane == __ffs(h2) - 1) x = NEG_INF;
        float w3 = x;
        for (int off = 16; off; off >>= 1) w3 = fmaxf(w3, __shfl_xor_sync(0xffffffffu, w3, off));
        if (lane == 0) { swtop[wid] = w1; swtop[NWARP + wid] = w2; swtop[2 * NWARP + wid] = w3; }
    }
    __syncthreads();

    // ---- thr = 10th largest of 3*NWARP = 12 distinct seg1 elements.
    // Distinct row elements => >=10 row elements >= thr => thr <= row's 10th
    // largest: conservative row-wide. ----
    if (tid < 32) {
        float x = (lane < 3 * NWARP) ? swtop[lane] : NEG_INF;
        float t = NEG_INF;
        for (int r = 0; r < KSEL; ++r) {
            float bv = x;
            for (int off = 16; off; off >>= 1) bv = fmaxf(bv, __shfl_xor_sync(0xffffffffu, bv, off));
            unsigned holders = __ballot_sync(0xffffffffu, x == bv);
            if (lane == __ffs(holders) - 1) x = NEG_INF;   // retire one instance
            t = bv;
        }
        if (lane == 0) sthr = t;
    }
    __syncthreads();
    const float thr = sthr;

    // Quad filter: prefilter on quad max, push survivors (exact value+index).
    auto filter_quad = [&](float4 a, int i0) {
        float qm = fmaxf(fmaxf(a.x, a.y), fmaxf(a.z, a.w));
        if (qm >= thr) {                        // rare
            if (a.x >= thr) { unsigned p = atomicAdd(&scount, 1u); if (p < CAP) { cval[p] = a.x; cidx[p] = i0; } }
            if (a.y >= thr) { unsigned p = atomicAdd(&scount, 1u); if (p < CAP) { cval[p] = a.y; cidx[p] = i0 + 1; } }
            if (a.z >= thr) { unsigned p = atomicAdd(&scount, 1u); if (p < CAP) { cval[p] = a.z; cidx[p] = i0 + 2; } }
            if (a.w >= thr) { unsigned p = atomicAdd(&scount, 1u); if (p < CAP) { cval[p] = a.w; cidx[p] = i0 + 3; } }
        }
    };

    // ---- Phase 2: one filtered pass over the ENTIRE row (seg1 hits L1/L2) ----
    {
        int v = tid;
        for (; v + 3 * T < nv; v += 4 * T) {
            float4 a = rp4[v];
            float4 b = rp4[v + T];
            float4 c = rp4[v + 2 * T];
            float4 d = rp4[v + 3 * T];
            filter_quad(a, P + 4 * v);
            filter_quad(b, P + 4 * (v + T));
            filter_quad(c, P + 4 * (v + 2 * T));
            filter_quad(d, P + 4 * (v + 3 * T));
        }
        for (; v < nv; v += T) filter_quad(rp4[v], P + 4 * v);
    }
    if (tid == 0) {          // head elements, exact test
        for (int i = 0; i < P; ++i) {
            float x = rp[i];
            if (x >= thr) { unsigned p = atomicAdd(&scount, 1u); if (p < CAP) { cval[p] = x; cidx[p] = i; } }
        }
    }
    if (tid == 1) {          // tail elements, exact test
        for (int q = 0; q < tailn; ++q) {
            int i = P + 4 * nv + q;
            float x = rp[i];
            if (x >= thr) { unsigned p = atomicAdd(&scount, 1u); if (p < CAP) { cval[p] = x; cidx[p] = i; } }
        }
    }
    __syncthreads();

    const unsigned cnt   = scount;
    const int      stepv = step_ptr ? *step_ptr : KSEL;
    const float    base  = scores[row * score_last_dim + (stepv - 1)];

    if (cnt > CAP) {
        // Pathological mass-tie fallback: exact serial top-10.
        if (tid == 0) {
            float val[KSEL]; int idq[KSEL];
#pragma unroll
            for (int q = 0; q < KSEL; ++q) { val[q] = NEG_INF; idq[q] = IDX_INF; }
            for (int i = 0; i < VOCAB; ++i) {
                float x = rp[i];
                if (better(x, i, val[KSEL - 1], idq[KSEL - 1])) {
                    val[KSEL - 1] = x; idq[KSEL - 1] = i;
#pragma unroll
                    for (int q = KSEL - 1; q > 0; --q) {
                        if (better(val[q], idq[q], val[q - 1], idq[q - 1])) {
                            float tv = val[q]; val[q] = val[q - 1]; val[q - 1] = tv;
                            int   ti = idq[q]; idq[q] = idq[q - 1]; idq[q - 1] = ti;
                        }
                    }
                }
            }
#pragma unroll
            for (int r = 0; r < KSEL; ++r) {
                g_cand_val[row * KSEL + r] = (val[r] + base) - (float)(r + 1) * DIV_RATE;
                g_cand_idx[row * KSEL + r] = idq[r];
            }
        }
    } else {
        // Warp-parallel stable top-10 over ~50 exact candidates.
        if (tid < 32) {
            for (int r = 0; r < KSEL; ++r) {
                float bv = NEG_INF; int bi = IDX_INF; int bp = -1;
                for (unsigned c = lane; c < cnt; c += 32) {
                    float x = cval[c]; int ix = cidx[c];
                    if (better(x, ix, bv, bi)) { bv = x; bi = ix; bp = (int)c; }
                }
                for (int off = 16; off; off >>= 1) {
                    float ov = __shfl_down_sync(0xffffffffu, bv, off);
                    int   oi = __shfl_down_sync(0xffffffffu, bi, off);
                    int   op = __shfl_down_sync(0xffffffffu, bp, off);
                    if (better(ov, oi, bv, bi)) { bv = ov; bi = oi; bp = op; }
                }
                if (lane == 0) {
                    // ((lprob + base) - penalty): reference op order -> bit-exact.
                    g_cand_val[row * KSEL + r] = (bv + base) - (float)(r + 1) * DIV_RATE;
                    g_cand_idx[row * KSEL + r] = bi;
                    cval[bp] = NEG_INF; cidx[bp] = IDX_INF;
                }
                __syncwarp();
            }
        }
    }

    // ---- Fused finisher: last beam-block of the batch does the 50->10 select ----
    int done = 0;
    if (tid == 0) {
        __threadfence();                              // release g_cand writes
        done = atomicAdd(&g_batch_done[batch], 1);
    }
    if (tid < 32) {
        done = __shfl_sync(0xffffffffu, done, 0);
        if (done == BEAM - 1) {
            __threadfence();                          // acquire peers' g_cand
            const int b50 = batch * BEAM * KSEL;
            float v0 = NEG_INF, v1 = NEG_INF;
            int   p0 = IDX_INF, p1 = IDX_INF;
            if (lane < BEAM * KSEL)      { v0 = __ldcg(&g_cand_val[b50 + lane]);      p0 = lane; }
            if (lane + 32 < BEAM * KSEL) { v1 = __ldcg(&g_cand_val[b50 + lane + 32]); p1 = lane + 32; }
            for (int r = 0; r < KSEL; ++r) {
                float bv; int bp;
                if (better(v0, p0, v1, p1)) { bv = v0; bp = p0; } else { bv = v1; bp = p1; }
                for (int off = 16; off; off >>= 1) {
                    float ov = __shfl_down_sync(0xffffffffu, bv, off);
                    int   op = __shfl_down_sync(0xffffffffu, bp, off);
                    if (better(ov, op, bv, bp)) { bv = ov; bp = op; }
                }
                bv = __shfl_sync(0xffffffffu, bv, 0);
                bp = __shfl_sync(0xffffffffu, bp, 0);
                if (lane == 0) {
                    out[batch * KSEL + r]                  = bv;                                   // scores
                    out[BSZ * KSEL + batch * KSEL + r]     = (float)__ldcg(&g_cand_idx[b50 + bp]); // indices
                    out[2 * BSZ * KSEL + batch * KSEL + r] = (float)(bp / KSEL);                   // beams
                }
                if (p0 == bp) { v0 = NEG_INF; p0 = IDX_INF; }
                if (p1 == bp) { v1 = NEG_INF; p1 = IDX_INF; }
            }
            if (lane == 0) atomicExch(&g_batch_done[batch], 0);   // reset for next replay
        }
    }
}

extern "C" void kernel_launch(void* const* d_in, const int* in_sizes, int n_in,
                              void* d_out, int out_size) {
    const float* lprobs = (const float*)d_in[0];
    const float* scores = (const float*)d_in[1];
    const int*   step   = (n_in >= 3) ? (const int*)d_in[2] : nullptr;
    const int score_last_dim = in_sizes[1] / ROWS;   // = 10

    dss_kernel<<<ROWS, T>>>(lprobs, scores, step, score_last_dim, (float*)d_out);
}